// round 1
// baseline (speedup 1.0000x reference)
#include <cuda_runtime.h>

// SparseEmbedding: out[b, :] = sum_n vals[b,n] * kernel[idx[b,n], :] + bias
// BATCH=4096, NNZ=32, VOCAB=1e6, DIM=64. All float32 except idx (int32).
//
// Strategy: one warp per batch row. Lane l owns output dims [2l, 2l+1] as a
// float2 accumulator. idx/vals for the row are loaded once (one per lane) and
// broadcast with __shfl_sync. Each nnz is a single coalesced 256B row load
// (LDG.64 x 32 lanes). Full unroll -> 32 independent loads in flight per warp.

#define BATCH 4096
#define NNZ   32
#define DIM   64

__global__ void __launch_bounds__(256) sparse_embedding_kernel(
    const int*   __restrict__ idx,
    const float* __restrict__ vals,
    const float* __restrict__ table,
    const float* __restrict__ bias,
    float*       __restrict__ out)
{
    const int gwarp = (blockIdx.x * blockDim.x + threadIdx.x) >> 5;
    const int lane  = threadIdx.x & 31;
    if (gwarp >= BATCH) return;

    // Each lane loads one (idx, val) pair for this row; broadcast in the loop.
    const int   my_idx = idx[gwarp * NNZ + lane];
    const float my_val = vals[gwarp * NNZ + lane];

    float2 acc = make_float2(0.0f, 0.0f);

#pragma unroll
    for (int n = 0; n < NNZ; ++n) {
        const int   id = __shfl_sync(0xffffffffu, my_idx, n);
        const float v  = __shfl_sync(0xffffffffu, my_val, n);
        const float2 kv = __ldg(reinterpret_cast<const float2*>(
            table + (size_t)id * DIM) + lane);
        acc.x = fmaf(v, kv.x, acc.x);
        acc.y = fmaf(v, kv.y, acc.y);
    }

    const float2 b = reinterpret_cast<const float2*>(bias)[lane];
    acc.x += b.x;
    acc.y += b.y;

    reinterpret_cast<float2*>(out + (size_t)gwarp * DIM)[lane] = acc;
}

extern "C" void kernel_launch(void* const* d_in, const int* in_sizes, int n_in,
                              void* d_out, int out_size)
{
    const int*   idx   = (const int*)  d_in[0];
    const float* vals  = (const float*)d_in[1];
    const float* table = (const float*)d_in[2];
    const float* bias  = (const float*)d_in[3];
    float*       out   = (float*)d_out;

    // 4096 warps total, 8 warps (256 threads) per block -> 512 blocks.
    const int threads = 256;
    const int blocks  = (BATCH * 32) / threads;
    sparse_embedding_kernel<<<blocks, threads>>>(idx, vals, table, bias, out);
}